// round 4
// baseline (speedup 1.0000x reference)
#include <cuda_runtime.h>
#include <cuda_fp16.h>
#include <cstdint>

// Dims: B=64, S=2048, D=H=768, L=2
#define NE 100663296           // S*B*H
#define OUT0 100663296         // offset of h_fin in flattened output

// ---------------- scratch (__device__ globals; no allocs) ----------------
__device__ __half g_xh[NE];            // x in fp16 (layout [B,S,D])
__device__ __half g_wh[2 * 3072 * 768];
__device__ float  g_bc[2 * 3072];      // b_ih + b_hh
__device__ __half g_F[NE];             // sigmoid(f)
__device__ __half g_IG[NE];            // sigmoid(i)*tanh(g)
__device__ __half g_O[NE];             // sigmoid(o)
__device__ __half g_H[NE];             // layer0 h output (time-major)

// ---------------- fast activations ----------------
__device__ __forceinline__ float fsig(float x) {
    return __fdividef(1.0f, 1.0f + __expf(-x));
}
__device__ __forceinline__ float ftanh(float x) {
    return __fdividef(2.0f, 1.0f + __expf(-2.0f * x)) - 1.0f;
}

// ---------------- PTX helpers ----------------
__device__ __forceinline__ void cp16(uint32_t dst, const void* src) {
    asm volatile("cp.async.ca.shared.global [%0], [%1], 16;\n" :: "r"(dst), "l"(src));
}
__device__ __forceinline__ void cp_commit() { asm volatile("cp.async.commit_group;\n"); }
template<int N> __device__ __forceinline__ void cp_wait() {
    asm volatile("cp.async.wait_group %0;\n" :: "n"(N));
}
__device__ __forceinline__ void ldsm4(uint32_t* r, uint32_t a) {
    asm volatile("ldmatrix.sync.aligned.m8n8.x4.shared.b16 {%0,%1,%2,%3}, [%4];\n"
                 : "=r"(r[0]), "=r"(r[1]), "=r"(r[2]), "=r"(r[3]) : "r"(a));
}
__device__ __forceinline__ void mma16816(float* c, const uint32_t* a, const uint32_t* b) {
    asm volatile(
        "mma.sync.aligned.m16n8k16.row.col.f32.f16.f16.f32 "
        "{%0,%1,%2,%3}, {%4,%5,%6,%7}, {%8,%9}, {%0,%1,%2,%3};\n"
        : "+f"(c[0]), "+f"(c[1]), "+f"(c[2]), "+f"(c[3])
        : "r"(a[0]), "r"(a[1]), "r"(a[2]), "r"(a[3]), "r"(b[0]), "r"(b[1]));
}

// ---------------- converters ----------------
__global__ void cvt_x_kernel(const float4* __restrict__ x) {
    int i = blockIdx.x * blockDim.x + threadIdx.x;      // < NE/4
    float4 v = x[i];
    __half2* d = (__half2*)g_xh;
    d[2 * i]     = __floats2half2_rn(v.x, v.y);
    d[2 * i + 1] = __floats2half2_rn(v.z, v.w);
}
__global__ void cvt_w_kernel(const float* __restrict__ W,
                             const float* __restrict__ bih,
                             const float* __restrict__ bhh) {
    int i = blockIdx.x * blockDim.x + threadIdx.x;      // < 2*3072*768
    g_wh[i] = __float2half(W[i]);
    if (i < 2 * 3072) g_bc[i] = bih[i] + bhh[i];
}

// ---------------- fused GEMM + gate activation ----------------
// Block tile: 128 rows (m = t*64+b, time-major) x 128 cols (4 gates x 32 h).
// Layer 0 remaps rows into x's [B,S,D] layout; layer 1 reads g_H directly.
template<int LAYER>
__device__ __forceinline__ void load_stage(char* smem, int stage, int k0, int tid,
                                           int rowTile, int h0,
                                           const __half* Ag, const __half* Wg) {
    char* sA = smem + stage * 10240;
    char* sB = smem + 20480 + stage * 10240;
#pragma unroll
    for (int i = 0; i < 2; i++) {
        int chunk = tid + 256 * i;          // 0..511
        int row = chunk >> 2;               // 0..127
        int kc = chunk & 3;                 // 16B chunk
        int rg = rowTile + row;
        int sr = (LAYER == 0) ? (((rg & 63) << 11) | (rg >> 6)) : rg;  // b*2048+t
        cp16((uint32_t)__cvta_generic_to_shared(sA + row * 80 + kc * 16),
             Ag + (size_t)sr * 768 + k0 + kc * 8);
    }
#pragma unroll
    for (int i = 0; i < 2; i++) {
        int chunk = tid + 256 * i;
        int bn = chunk >> 2;                // local col 0..127
        int kc = chunk & 3;
        int wrow = (bn >> 5) * 768 + h0 + (bn & 31);   // gate*768 + h
        cp16((uint32_t)__cvta_generic_to_shared(sB + bn * 80 + kc * 16),
             Wg + (size_t)wrow * 768 + k0 + kc * 8);
    }
}

template<int LAYER>
__global__ void __launch_bounds__(256, 2) gemm_gates() {
    extern __shared__ char smem[];
    const __half* Ag = (LAYER == 0) ? g_xh : g_H;
    const __half* Wg = g_wh + LAYER * (3072 * 768);
    const float* bias = g_bc + LAYER * 3072;

    int h0 = blockIdx.x * 32;
    int rowTile = blockIdx.y * 128;
    int tid = threadIdx.x;
    int lane = tid & 31;
    int warp = tid >> 5;
    int wm = (warp & 1) * 64;
    int wn = (warp >> 1) * 32;

    float acc[4][4][4];
#pragma unroll
    for (int a = 0; a < 4; a++)
#pragma unroll
        for (int b = 0; b < 4; b++)
#pragma unroll
            for (int d = 0; d < 4; d++) acc[a][b][d] = 0.0f;

    load_stage<LAYER>(smem, 0, 0, tid, rowTile, h0, Ag, Wg);
    cp_commit();

    for (int kt = 0; kt < 24; kt++) {
        if (kt + 1 < 24) {
            load_stage<LAYER>(smem, (kt + 1) & 1, (kt + 1) * 32, tid, rowTile, h0, Ag, Wg);
            cp_commit();
            cp_wait<1>();
        } else {
            cp_wait<0>();
        }
        __syncthreads();
        char* sA = smem + (kt & 1) * 10240;
        char* sB = smem + 20480 + (kt & 1) * 10240;
#pragma unroll
        for (int k16 = 0; k16 < 2; k16++) {
            uint32_t af[4][4];
#pragma unroll
            for (int mt = 0; mt < 4; mt++) {
                int row = wm + mt * 16 + (lane & 15);
                int col = k16 * 16 + (lane >> 4) * 8;
                ldsm4(af[mt], (uint32_t)__cvta_generic_to_shared(sA + row * 80 + col * 2));
            }
            uint32_t bf[4][2];
#pragma unroll
            for (int nt2 = 0; nt2 < 2; nt2++) {
                int n = wn + nt2 * 16 + (lane & 7) + ((lane >> 4) & 1) * 8;
                int kk = k16 * 16 + ((lane >> 3) & 1) * 8;
                uint32_t r[4];
                ldsm4(r, (uint32_t)__cvta_generic_to_shared(sB + n * 80 + kk * 2));
                bf[nt2 * 2][0] = r[0];     bf[nt2 * 2][1] = r[1];
                bf[nt2 * 2 + 1][0] = r[2]; bf[nt2 * 2 + 1][1] = r[3];
            }
#pragma unroll
            for (int mt = 0; mt < 4; mt++)
#pragma unroll
                for (int nt = 0; nt < 4; nt++)
                    mma16816(acc[mt][nt], af[mt], bf[nt]);
        }
        __syncthreads();
    }

    // stage accumulators to smem so each thread can gather all 4 gates of one (row,h)
    float* sC = (float*)smem;
#pragma unroll
    for (int mt = 0; mt < 4; mt++)
#pragma unroll
        for (int nt = 0; nt < 4; nt++) {
            int r0 = wm + mt * 16 + (lane >> 2);
            int c0 = wn + nt * 8 + (lane & 3) * 2;
            sC[r0 * 132 + c0]           = acc[mt][nt][0];
            sC[r0 * 132 + c0 + 1]       = acc[mt][nt][1];
            sC[(r0 + 8) * 132 + c0]     = acc[mt][nt][2];
            sC[(r0 + 8) * 132 + c0 + 1] = acc[mt][nt][3];
        }
    __syncthreads();

    int hl = tid & 31;
    float bi = bias[h0 + hl];
    float bfv = bias[768 + h0 + hl];
    float bg = bias[1536 + h0 + hl];
    float bo = bias[2304 + h0 + hl];
#pragma unroll 4
    for (int it = 0; it < 16; it++) {
        int r = (tid >> 5) + it * 8;
        float gi = sC[r * 132 + hl] + bi;
        float gf = sC[r * 132 + 32 + hl] + bfv;
        float gg = sC[r * 132 + 64 + hl] + bg;
        float go = sC[r * 132 + 96 + hl] + bo;
        float fi = fsig(gi);
        float ff = fsig(gf);
        float fg = ftanh(gg);
        float fo = fsig(go);
        size_t o = (size_t)(rowTile + r) * 768 + h0 + hl;
        g_F[o]  = __float2half(ff);
        g_IG[o] = __float2half(fi * fg);
        g_O[o]  = __float2half(fo);
    }
}

// ---------------- sequential cell-state scan ----------------
// One thread per (b,h) column; 2048 steps; coalesced fp16 reads; unroll-8 MLP.
template<int LAYER>
__global__ void __launch_bounds__(128) scan_kernel(const int* __restrict__ parts,
                                                   float* __restrict__ out) {
    __shared__ unsigned char rst[2048];
    int b = blockIdx.y;
    int h = blockIdx.x * 128 + threadIdx.x;
    if (LAYER == 0) {
        for (int t = threadIdx.x; t < 2048; t += 128) {
            rst[t] = (t == 0) ? 1
                     : (unsigned char)(__ldg(parts + t) != __ldg(parts + t - 1));
        }
        __syncthreads();
    }
    float c = 0.0f, hv = 0.0f;
#pragma unroll 8
    for (int t = 0; t < 2048; t++) {
        size_t idx = (size_t)(t * 64 + b) * 768 + h;
        float f  = __half2float(g_F[idx]);
        float ig = __half2float(g_IG[idx]);
        float o  = __half2float(g_O[idx]);
        if (LAYER == 0) { if (rst[t]) c = 0.0f; }
        c = __fmaf_rn(f, c, ig);
        hv = o * ftanh(c);
        if (LAYER == 0) g_H[idx] = __float2half(hv);
        else            out[idx] = hv;
    }
    int off = b * 768 + h;
    out[OUT0 + LAYER * 49152 + off]         = hv;   // h_fin[layer]
    out[OUT0 + 98304 + LAYER * 49152 + off] = c;    // c_fin[layer]
}

// ---------------- launcher ----------------
extern "C" void kernel_launch(void* const* d_in, const int* in_sizes, int n_in,
                              void* d_out, int out_size) {
    const float* x    = (const float*)d_in[0];
    const float* W_ih = (const float*)d_in[1];
    // d_in[2] = W_hh — unused: the reference feeds h0 = zeros into every cell
    const float* b_ih = (const float*)d_in[3];
    const float* b_hh = (const float*)d_in[4];
    const int* parts  = (const int*)d_in[5];
    float* out = (float*)d_out;
    (void)in_sizes; (void)n_in; (void)out_size;

    cudaFuncSetAttribute(gemm_gates<0>, cudaFuncAttributeMaxDynamicSharedMemorySize, 67584);
    cudaFuncSetAttribute(gemm_gates<1>, cudaFuncAttributeMaxDynamicSharedMemorySize, 67584);

    cvt_x_kernel<<<98304, 256>>>((const float4*)x);
    cvt_w_kernel<<<18432, 256>>>(W_ih, b_ih, b_hh);

    gemm_gates<0><<<dim3(24, 1024), 256, 67584>>>();
    scan_kernel<0><<<dim3(6, 64), 128>>>(parts, out);
    gemm_gates<1><<<dim3(24, 1024), 256, 67584>>>();
    scan_kernel<1><<<dim3(6, 64), 128>>>(parts, out);
}